// round 15
// baseline (speedup 1.0000x reference)
#include <cuda_runtime.h>

// Heirachical_Loss — closed-form collapse of the hierarchy matmul.
//
// loss = B - sum_i [ 0.5*S_all + 0.25*S100(t) + 0.125*S10(t) + 0.125*outputs[i,t] ]
//
// Producer blocks: R2 main structure verbatim (best measured 23.6us).
// Completion signal is a fire-and-forget red.release.gpu.add (no return
// value -> no thread ever waits on it; CTA exits immediately). One extra
// dedicated reducer block spin-waits (acquire + nanosleep) for all
// producers, then does a single parallel padded read + deterministic
// fixed-order tree. No second launch (fixed ~4.5us), no blocking epilogue
// (fixed ~4us). Counter reset by the reducer each run -> graph-replay safe.

#define HL_C           1000
#define ROWS_PER_BLOCK 8
#define HL_THREADS     256
#define PAD_PARTIALS   4096                 // fixed padded read range (floats)
#define MAX_BLOCKS     8192

__device__ float        g_hl_partials[MAX_BLOCKS];   // zero-init .bss
__device__ unsigned int g_hl_count = 0;

__device__ __forceinline__ void red_add_release_gpu(unsigned* addr)
{
    asm volatile("red.release.gpu.global.add.u32 [%0], 1;"
                 :: "l"(addr) : "memory");
}

__device__ __forceinline__ unsigned ld_acquire_gpu_u32(const unsigned* addr)
{
    unsigned v;
    asm volatile("ld.acquire.gpu.global.u32 %0, [%1];"
                 : "=r"(v) : "l"(addr) : "memory");
    return v;
}

__global__ void __launch_bounds__(HL_THREADS) hloss_fused(
    const float* __restrict__ outputs,
    const int*   __restrict__ target,
    float*       __restrict__ out,
    int B, int nprod)
{
    const int tid = threadIdx.x;

    // ================= Reducer block (dispatched last, bid == nprod) =========
    if (blockIdx.x == (unsigned)nprod) {
        if (tid == 0) {
            // Spin until every producer's release-add has landed.
            unsigned c;
            while ((c = ld_acquire_gpu_u32(&g_hl_count)) < (unsigned)nprod)
                __nanosleep(64);
            g_hl_count = 0;          // reset for next graph replay
        }
        __syncthreads();             // acquire + barrier: partials visible to block

        float a = 0.f;
        if (nprod <= PAD_PARTIALS) {
            // 4096 floats = 1024 float4; 4 per thread, front-batched.
            // Entries >= nprod were never written -> 0 (.bss zero-init).
            const float4* pp = (const float4*)g_hl_partials;
            float4 q[4];
#pragma unroll
            for (int k = 0; k < 4; ++k)
                q[k] = pp[k * HL_THREADS + tid];
#pragma unroll
            for (int k = 0; k < 4; ++k)
                a += (q[k].x + q[k].y) + (q[k].z + q[k].w);
        } else {
            for (int i = tid; i < nprod; i += HL_THREADS)
                a += g_hl_partials[i];
        }
        __shared__ float sm[HL_THREADS];
        sm[tid] = a;
        __syncthreads();
#pragma unroll
        for (int s2 = HL_THREADS / 2; s2; s2 >>= 1) {
            if (tid < s2) sm[tid] += sm[tid + s2];
            __syncthreads();
        }
        if (tid == 0) out[0] = sm[0];
        return;
    }

    // ================= Producer blocks: R2 main verbatim ======================
    const int warp = tid >> 5;
    const int lane = tid & 31;
    const int row  = blockIdx.x * ROWS_PER_BLOCK + warp;

    float win = 0.0f;
    if (row < B) {
        const int t = target[row];
        const float4* __restrict__ p =
            (const float4*)(outputs + (size_t)row * HL_C);

        // ---- Phase 1: full-row sum (250 float4 per row, front-batched) ----
        float4 v[7];
#pragma unroll
        for (int it = 0; it < 7; ++it)
            v[it] = p[it * 32 + lane];            // float4 idx 0..223
        float4 vt = make_float4(0.f, 0.f, 0.f, 0.f);
        if (lane < 26)
            vt = p[224 + lane];                   // idx 224..249

        float s = (vt.x + vt.y) + (vt.z + vt.w);
#pragma unroll
        for (int it = 0; it < 7; ++it)
            s += (v[it].x + v[it].y) + (v[it].z + v[it].w);

        // ---- Phase 2: target's 100-block (L1 hit — just loaded) ----
        const int lo100 = (t / 100) * 100;        // 4-aligned
        const int lo10  = (t / 10)  * 10;
        float s100 = 0.f, s10 = 0.f, ot = 0.f;
        if (lane < 25) {
            float4 q = p[(lo100 >> 2) + lane];
            const int e0 = lo100 + lane * 4;
            float vals[4] = { q.x, q.y, q.z, q.w };
#pragma unroll
            for (int m = 0; m < 4; ++m) {
                const int e = e0 + m;
                const float vv = vals[m];
                s100 += vv;
                if ((unsigned)(e - lo10) < 10u) s10 += vv;
                if (e == t)                     ot  = vv;
            }
        }

        float part = 0.5f * s + 0.25f * s100 + 0.125f * s10 + 0.125f * ot;
#pragma unroll
        for (int off = 16; off; off >>= 1)
            part += __shfl_xor_sync(0xffffffffu, part, off);
        win = part;
    }

    // ---- Block reduce, then fire-and-forget completion signal ----
    __shared__ float ws[ROWS_PER_BLOCK];
    if (lane == 0)
        ws[warp] = (row < B) ? (1.0f - win) : 0.0f;
    __syncthreads();
    if (tid == 0) {
        float acc = 0.f;
#pragma unroll
        for (int w = 0; w < ROWS_PER_BLOCK; ++w) acc += ws[w];
        g_hl_partials[blockIdx.x] = acc;
        // release-add orders the partial store before the count bump (L2),
        // returns nothing -> nobody waits; CTA exits immediately.
        red_add_release_gpu(&g_hl_count);
    }
}

extern "C" void kernel_launch(void* const* d_in, const int* in_sizes, int n_in,
                              void* d_out, int out_size)
{
    // metadata order: outputs [B*1000] float32, target [B] int32.
    int i_o = 0, i_t = 1;
    if (n_in >= 2 && in_sizes[1] > in_sizes[0]) { i_o = 1; i_t = 0; }

    const float* outputs = (const float*)d_in[i_o];
    const int*   target  = (const int*)d_in[i_t];
    const int B = in_sizes[i_t];

    int nprod = (B + ROWS_PER_BLOCK - 1) / ROWS_PER_BLOCK;   // 4096 for B=32768
    if (nprod > MAX_BLOCKS) nprod = MAX_BLOCKS;

    hloss_fused<<<nprod + 1, HL_THREADS>>>(outputs, target, (float*)d_out, B, nprod);
}

// round 16
// speedup vs baseline: 1.0767x; 1.0767x over previous
#include <cuda_runtime.h>

// Heirachical_Loss — closed-form collapse of the hierarchy matmul.
//
// loss = B - sum_i [ 0.5*S_all + 0.25*S100(t) + 0.125*S10(t) + 0.125*outputs[i,t] ]
//
// Two kernels. Main: R2 structure verbatim (best measured, ~23.6us,
// ~5.6 TB/s). Reduce: launched with Programmatic Dependent Launch
// (programmaticStreamSerializationAllowed=1) so its launch/ramp overlaps
// the main kernel's tail; cudaGridDependencySynchronize() inside gates all
// reads until the primary grid's memory is visible. Deterministic
// fixed-order reduction; no device sync state -> trivially replay-safe.

#define HL_C           1000
#define ROWS_PER_BLOCK 8
#define HL_THREADS     256
#define PAD_PARTIALS   4096
#define MAX_BLOCKS     8192

__device__ float g_hl_partials[MAX_BLOCKS];   // zero-init .bss; idx>=nblocks never written

__global__ void __launch_bounds__(HL_THREADS) hloss_main(
    const float* __restrict__ outputs,
    const int*   __restrict__ target,
    int B)
{
    const int warp = threadIdx.x >> 5;
    const int lane = threadIdx.x & 31;
    const int row  = blockIdx.x * ROWS_PER_BLOCK + warp;

    float win = 0.0f;
    if (row < B) {
        const int t = target[row];
        const float4* __restrict__ p =
            (const float4*)(outputs + (size_t)row * HL_C);

        // ---- Phase 1: full-row sum (250 float4 per row, front-batched) ----
        float4 v[7];
#pragma unroll
        for (int it = 0; it < 7; ++it)
            v[it] = p[it * 32 + lane];            // float4 idx 0..223
        float4 vt = make_float4(0.f, 0.f, 0.f, 0.f);
        if (lane < 26)
            vt = p[224 + lane];                   // idx 224..249

        float s = (vt.x + vt.y) + (vt.z + vt.w);
#pragma unroll
        for (int it = 0; it < 7; ++it)
            s += (v[it].x + v[it].y) + (v[it].z + v[it].w);

        // ---- Phase 2: target's 100-block (L1 hit — just loaded) ----
        const int lo100 = (t / 100) * 100;        // 4-aligned
        const int lo10  = (t / 10)  * 10;
        float s100 = 0.f, s10 = 0.f, ot = 0.f;
        if (lane < 25) {
            float4 q = p[(lo100 >> 2) + lane];
            const int e0 = lo100 + lane * 4;
            float vals[4] = { q.x, q.y, q.z, q.w };
#pragma unroll
            for (int m = 0; m < 4; ++m) {
                const int e = e0 + m;
                const float vv = vals[m];
                s100 += vv;
                if ((unsigned)(e - lo10) < 10u) s10 += vv;
                if (e == t)                     ot  = vv;
            }
        }

        float part = 0.5f * s + 0.25f * s100 + 0.125f * s10 + 0.125f * ot;
#pragma unroll
        for (int off = 16; off; off >>= 1)
            part += __shfl_xor_sync(0xffffffffu, part, off);
        win = part;
    }

    // ---- Block reduce: one win per warp -> per-block partial of (1 - win) ----
    __shared__ float ws[ROWS_PER_BLOCK];
    if (lane == 0)
        ws[warp] = (row < B) ? (1.0f - win) : 0.0f;
    __syncthreads();
    if (threadIdx.x == 0) {
        float acc = 0.f;
#pragma unroll
        for (int w = 0; w < ROWS_PER_BLOCK; ++w) acc += ws[w];
        g_hl_partials[blockIdx.x] = acc;
    }
}

// PDL secondary: launches while hloss_main is still draining; the grid
// dependency sync gates the reads. Fixed padded 4096-float read = 4
// front-batched float4s per thread, one parallel round-trip, then a
// deterministic shared-memory tree.
__global__ void __launch_bounds__(HL_THREADS) hloss_reduce(float* __restrict__ out, int n)
{
    cudaGridDependencySynchronize();   // primary grid complete + memory visible

    const int tid = threadIdx.x;
    float a = 0.f;
    if (n <= PAD_PARTIALS) {
        const float4* pp = (const float4*)g_hl_partials;
        float4 q[4];
#pragma unroll
        for (int k = 0; k < 4; ++k)
            q[k] = pp[k * HL_THREADS + tid];
#pragma unroll
        for (int k = 0; k < 4; ++k)
            a += (q[k].x + q[k].y) + (q[k].z + q[k].w);
    } else {
        for (int i = tid; i < n; i += HL_THREADS)
            a += g_hl_partials[i];
    }
    __shared__ float sm[HL_THREADS];
    sm[tid] = a;
    __syncthreads();
#pragma unroll
    for (int s2 = HL_THREADS / 2; s2; s2 >>= 1) {
        if (tid < s2) sm[tid] += sm[tid + s2];
        __syncthreads();
    }
    if (tid == 0) out[0] = sm[0];
}

extern "C" void kernel_launch(void* const* d_in, const int* in_sizes, int n_in,
                              void* d_out, int out_size)
{
    // metadata order: outputs [B*1000] float32, target [B] int32.
    int i_o = 0, i_t = 1;
    if (n_in >= 2 && in_sizes[1] > in_sizes[0]) { i_o = 1; i_t = 0; }

    const float* outputs = (const float*)d_in[i_o];
    const int*   target  = (const int*)d_in[i_t];
    const int B = in_sizes[i_t];

    int nblocks = (B + ROWS_PER_BLOCK - 1) / ROWS_PER_BLOCK;  // 4096 for B=32768
    if (nblocks > MAX_BLOCKS) nblocks = MAX_BLOCKS;

    hloss_main<<<nblocks, HL_THREADS>>>(outputs, target, B);

    // Secondary with Programmatic Dependent Launch: overlap its launch/ramp
    // with the primary's tail. Falls back to a plain launch if PDL launch fails.
    cudaLaunchConfig_t cfg = {};
    cfg.gridDim  = dim3(1, 1, 1);
    cfg.blockDim = dim3(HL_THREADS, 1, 1);
    cfg.dynamicSmemBytes = 0;
    cfg.stream = 0;
    cudaLaunchAttribute attr[1];
    attr[0].id = cudaLaunchAttributeProgrammaticStreamSerialization;
    attr[0].val.programmaticStreamSerializationAllowed = 1;
    cfg.attrs = attr;
    cfg.numAttrs = 1;

    cudaError_t e = cudaLaunchKernelEx(&cfg, hloss_reduce, (float*)d_out, nblocks);
    if (e != cudaSuccess) {
        // PDL unsupported in this capture context -> plain serialized launch.
        hloss_reduce<<<1, HL_THREADS>>>((float*)d_out, nblocks);
    }
}